// round 16
// baseline (speedup 1.0000x reference)
#include <cuda_runtime.h>
#include <cuda_fp16.h>
#include <math.h>
#include <stdint.h>

#define HID    1024
#define INP    512
#define BATCH  64
#define TT     512
#define RGRID  128
#define NTHR   256

// recurrence smem: shared (kq,cc) A regions + reduction buffer
#define AW_STR   72                         // halves per row (64 + 8 pad)
#define AREG_B   (32 * AW_STR * 2)          // one (kq,cc) region: 4608 B
#define A_TOT_B  (16 * AREG_B)              // 4 kq x 4 cc: 73728 B
#define RED_B    (8 * 6 * 128 * 4)          // 24576 B
#define RSMEM_BYTES (A_TOT_B + RED_B)

// igemm smem (fused 3-gate): xs[2][128*IG_STR] + ws[2][3][64*IG_STR] halves
#define IG_STR 40
#define IGS_X  (128 * IG_STR)
#define IGS_W  (64 * IG_STR)
#define IGSM_BYTES ((2 * IGS_X + 6 * IGS_W) * 2)

// Scratch (device globals — allocation-free contract)
// packed input projections: [b][t][h][4] halves = {r, z, n, pad}
__device__ __half g_xgp[(size_t)BATCH * TT * HID * 4];
__device__ __half g_xh[(size_t)BATCH * TT * INP];      // fp16 copy of x
__device__ __half g_wih[3][HID * INP];                 // fp16 copies of W_i_{r,z,n}
__device__ __half g_h[BATCH * HID];                    // hidden state (fp16)
__device__ unsigned g_cnt[64];                         // split barrier counters (g_cnt[0], g_cnt[32])

// ---------------------------------------------------------------------------
__device__ __forceinline__ void mma_f16(float c[4], uint32_t a0, uint32_t a1,
                                        uint32_t a2, uint32_t a3,
                                        uint32_t b0, uint32_t b1) {
    asm volatile(
        "mma.sync.aligned.m16n8k16.row.col.f32.f16.f16.f32 "
        "{%0,%1,%2,%3}, {%4,%5,%6,%7}, {%8,%9}, {%0,%1,%2,%3};\n"
        : "+f"(c[0]), "+f"(c[1]), "+f"(c[2]), "+f"(c[3])
        : "r"(a0), "r"(a1), "r"(a2), "r"(a3), "r"(b0), "r"(b1));
}

__device__ __forceinline__ void ldsm_x4(uint32_t& r0, uint32_t& r1,
                                        uint32_t& r2, uint32_t& r3, uint32_t addr) {
    asm volatile("ldmatrix.sync.aligned.m8n8.x4.shared.b16 {%0,%1,%2,%3}, [%4];"
                 : "=r"(r0), "=r"(r1), "=r"(r2), "=r"(r3) : "r"(addr));
}

__device__ __forceinline__ void cp16ca(void* dst, const void* src) {
    uint32_t d = (uint32_t)__cvta_generic_to_shared(dst);
    asm volatile("cp.async.ca.shared.global [%0], [%1], 16;\n" :: "r"(d), "l"(src));
}
__device__ __forceinline__ void cp16cg(void* dst, const void* src) {
    uint32_t d = (uint32_t)__cvta_generic_to_shared(dst);
    asm volatile("cp.async.cg.shared.global [%0], [%1], 16;\n" :: "r"(d), "l"(src));
}
__device__ __forceinline__ void cp_commit() { asm volatile("cp.async.commit_group;\n"); }

__device__ __forceinline__ float sigmoidf_fast(float x) {
    return 1.0f / (1.0f + __expf(-x));
}
__device__ __forceinline__ float tanhf_fast(float x) {
    return 2.0f / (1.0f + __expf(-2.0f * x)) - 1.0f;
}

// ---------------------------------------------------------------------------
__global__ void reset_kernel()
{
    int i = blockIdx.x * blockDim.x + threadIdx.x;
    if (i < 64) g_cnt[i] = 0u;
    if (i < BATCH * HID) g_h[i] = __float2half(0.0f);
}

// ---------------------------------------------------------------------------
// Convert x and W_i_* to fp16 (one-time pre-pass).
__global__ __launch_bounds__(256) void convert_kernel(
    const float* __restrict__ x,
    const float* __restrict__ Wr, const float* __restrict__ Wz, const float* __restrict__ Wn)
{
    const size_t stride = (size_t)gridDim.x * blockDim.x;
    const size_t i0 = (size_t)blockIdx.x * blockDim.x + threadIdx.x;

    const size_t NX4 = (size_t)BATCH * TT * INP / 4;
    for (size_t j = i0; j < NX4; j += stride) {
        float4 v = ((const float4*)x)[j];
        ((__half2*)g_xh)[j * 2]     = __floats2half2_rn(v.x, v.y);
        ((__half2*)g_xh)[j * 2 + 1] = __floats2half2_rn(v.z, v.w);
    }
    const size_t NW4 = (size_t)HID * INP / 4;
    for (size_t j = i0; j < NW4; j += stride) {
        float4 a = ((const float4*)Wr)[j];
        float4 b = ((const float4*)Wz)[j];
        float4 c = ((const float4*)Wn)[j];
        ((__half2*)g_wih[0])[j * 2]     = __floats2half2_rn(a.x, a.y);
        ((__half2*)g_wih[0])[j * 2 + 1] = __floats2half2_rn(a.z, a.w);
        ((__half2*)g_wih[1])[j * 2]     = __floats2half2_rn(b.x, b.y);
        ((__half2*)g_wih[1])[j * 2 + 1] = __floats2half2_rn(b.z, b.w);
        ((__half2*)g_wih[2])[j * 2]     = __floats2half2_rn(c.x, c.y);
        ((__half2*)g_wih[2])[j * 2 + 1] = __floats2half2_rn(c.z, c.w);
    }
}

// ---------------------------------------------------------------------------
// Input projection GEMM, fused over the 3 gates (fp16 MMA m16n8k16).
// Epilogue packs {r,z,n} as fp16 into g_xgp[b][t][h][4].
__global__ __launch_bounds__(256) void igemm_f16_fused(
    const float* __restrict__ br, const float* __restrict__ bz, const float* __restrict__ bn)
{
    extern __shared__ __half igs[];
    __half* xs = igs;                  // [2][IGS_X]
    __half* ws = igs + 2 * IGS_X;      // [2][3][IGS_W]

    const int m0 = blockIdx.y * 128;
    const int n0 = blockIdx.x * 64;
    const int tid  = threadIdx.x;
    const int w    = tid >> 5;
    const int lane = tid & 31;
    const int ar   = lane >> 2;
    const int ac   = lane & 3;
    const int wm   = w >> 1;
    const int wn   = w & 1;

    float acc[3][2][4][4];
#pragma unroll
    for (int g = 0; g < 3; g++)
#pragma unroll
        for (int mt = 0; mt < 2; mt++)
#pragma unroll
            for (int nt = 0; nt < 4; nt++)
#pragma unroll
                for (int q = 0; q < 4; q++) acc[g][mt][nt][q] = 0.0f;

    auto load_chunk = [&](int c) {
        const int k0 = c * 32;
        __half* xd = xs + (c & 1) * IGS_X;
        {
            int i = tid;
            int r = i >> 2, q = i & 3;
            cp16ca(&xd[r * IG_STR + q * 8], &g_xh[(size_t)(m0 + r) * INP + k0 + q * 8]);
            i = tid + 256; r = i >> 2; q = i & 3;
            cp16ca(&xd[r * IG_STR + q * 8], &g_xh[(size_t)(m0 + r) * INP + k0 + q * 8]);
        }
        __half* wd = ws + (c & 1) * (3 * IGS_W);
#pragma unroll
        for (int rep = 0; rep < 3; rep++) {
            const int job = tid + rep * 256;
            const int g  = job >> 8;
            const int rr = (job & 255) >> 2;
            const int q  = job & 3;
            cp16ca(&wd[g * IGS_W + rr * IG_STR + q * 8],
                   &g_wih[g][(size_t)(n0 + rr) * INP + k0 + q * 8]);
        }
        cp_commit();
    };

    load_chunk(0);

    for (int c = 0; c < INP / 32; c++) {
        asm volatile("cp.async.wait_group 0;\n");
        __syncthreads();
        if (c + 1 < INP / 32) load_chunk(c + 1);

        const __half* xb = xs + (c & 1) * IGS_X;
        const __half* wb = ws + (c & 1) * (3 * IGS_W);
        const uint32_t xb_base = (uint32_t)__cvta_generic_to_shared(xb);
        const uint32_t rowoff_b = 2u * ((uint32_t)(lane & 15) * IG_STR + (uint32_t)(lane >> 4) * 8);

#pragma unroll
        for (int s2 = 0; s2 < 2; s2++) {
            uint32_t afr[2][4];
#pragma unroll
            for (int mt = 0; mt < 2; mt++) {
                const uint32_t addr = xb_base
                    + 2u * (uint32_t)((wm * 32 + mt * 16) * IG_STR + s2 * 16)
                    + rowoff_b;
                ldsm_x4(afr[mt][0], afr[mt][1], afr[mt][2], afr[mt][3], addr);
            }
#pragma unroll
            for (int g = 0; g < 3; g++) {
#pragma unroll
                for (int nt = 0; nt < 4; nt++) {
                    const __half* bp = &wb[g * IGS_W
                        + (wn * 32 + nt * 8 + ar) * IG_STR + s2 * 16 + 2 * ac];
                    const uint32_t b0 = *(const uint32_t*)bp;
                    const uint32_t b1 = *(const uint32_t*)(bp + 8);
#pragma unroll
                    for (int mt = 0; mt < 2; mt++)
                        mma_f16(acc[g][mt][nt], afr[mt][0], afr[mt][1], afr[mt][2], afr[mt][3],
                                b0, b1);
                }
            }
        }
        __syncthreads();
    }

    // epilogue: pack {r,z,n} fp16 into g_xgp[b][t][h][4]
#pragma unroll
    for (int mt = 0; mt < 2; mt++) {
#pragma unroll
        for (int nt = 0; nt < 4; nt++) {
            const int h = n0 + wn * 32 + nt * 8 + ac * 2;
            const float br0 = br[h], br1 = br[h + 1];
            const float bz0 = bz[h], bz1 = bz[h + 1];
            const float bn0 = bn[h], bn1 = bn[h + 1];

#pragma unroll
            for (int half_ = 0; half_ < 2; half_++) {     // q pair: rows ar / ar+8
                const int row = m0 + wm * 32 + mt * 16 + ar + half_ * 8;
                const int b = row >> 9, t = row & (TT - 1);
                const size_t base = ((size_t)b * TT + t) * (size_t)HID;
                const int q0 = half_ * 2;

                // col h
                {
                    __half2 rz = __floats2half2_rn(acc[0][mt][nt][q0] + br0,
                                                   acc[1][mt][nt][q0] + bz0);
                    __half2 nn = __floats2half2_rn(acc[2][mt][nt][q0] + bn0, 0.0f);
                    uint2 u;
                    u.x = *(uint32_t*)&rz;
                    u.y = *(uint32_t*)&nn;
                    *(uint2*)&g_xgp[(base + h) * 4] = u;
                }
                // col h+1
                {
                    __half2 rz = __floats2half2_rn(acc[0][mt][nt][q0 + 1] + br1,
                                                   acc[1][mt][nt][q0 + 1] + bz1);
                    __half2 nn = __floats2half2_rn(acc[2][mt][nt][q0 + 1] + bn1, 0.0f);
                    uint2 u;
                    u.x = *(uint32_t*)&rz;
                    u.y = *(uint32_t*)&nn;
                    *(uint2*)&g_xgp[(base + h + 1) * 4] = u;
                }
            }
        }
    }
}

// ---------------------------------------------------------------------------
// Persistent recurrence kernel — R15 structure + split barrier (two disjoint
// 64-block domains by batch-half) + packed fp16 x operands.
__global__ __launch_bounds__(NTHR, 1) void recur_kernel(
    const float* __restrict__ Wr, const float* __restrict__ Wz, const float* __restrict__ Wn,
    const float* __restrict__ bhr, const float* __restrict__ bhz, const float* __restrict__ bhn,
    float* __restrict__ out)
{
    extern __shared__ char smc[];
    __half* As  = (__half*)smc;                 // [4 kq][4 cc][32 rows][AW_STR]
    float*  red = (float*)(smc + A_TOT_B);      // [8][6][128]

    const int tid  = threadIdx.x;
    const int bid  = blockIdx.x;
    const int w    = tid >> 5;
    const int lane = tid & 31;
    const int ar   = lane >> 2;
    const int ac   = lane & 3;

    const int cg  = bid >> 1;
    const int bh  = bid & 1;
    const int H0  = cg * 16;
    const int B0  = bh * 32;
    const int nh  = w >> 2;          // n-half (0..1): rows nh*24..+24
    const int kq  = w & 3;           // k-quarter (0..3)
    const int rot = bid & 3;         // chunk rotation

    unsigned* const cnt = &g_cnt[bh * 32];   // split barrier counter

    // epilogue mapping: col ec (0..15), batches B0+m0 and B0+m0+16
    const int ec = tid & 15;
    const int m0 = tid >> 4;         // 0..15
    const int hcol = H0 + ec;
    const float bR = __ldg(&bhr[hcol]);
    const float bZ = __ldg(&bhz[hcol]);
    const float bN = __ldg(&bhn[hcol]);

    // per-gate reduction coordinates (j = g*16 + ec)
    int nh_g[3], nt_g[3], jr_g[3];
#pragma unroll
    for (int g = 0; g < 3; g++) {
        const int j = g * 16 + ec;
        nh_g[g] = (j >= 24) ? 1 : 0;
        const int loc = j - nh_g[g] * 24;
        nt_g[g] = loc >> 3;
        jr_g[g] = loc & 7;
    }
    int rem_g[3];
#pragma unroll
    for (int g = 0; g < 3; g++)
        rem_g[g] = (m0 & 7) * 16 + (jr_g[g] >> 1) * 4 + (m0 >> 3) * 2 + (jr_g[g] & 1);

    // ---- W fragments into registers; slot cc holds k-range ((rot+cc)&3)*256 ----
    uint32_t wreg[4][4][3][2];
#pragma unroll
    for (int cc = 0; cc < 4; cc++) {
        const int kbase = ((rot + cc) & 3) * 256;
#pragma unroll
        for (int s2 = 0; s2 < 4; s2++)
#pragma unroll
            for (int nt = 0; nt < 3; nt++) {
                const int j    = nh * 24 + nt * 8 + ar;
                const int gate = j >> 4;
                const int col  = j & 15;
                const float* __restrict__ Wp = (gate == 0) ? Wr : ((gate == 1) ? Wz : Wn);
                const float* rowp = &Wp[(size_t)(H0 + col) * HID];
#pragma unroll
                for (int q = 0; q < 2; q++) {
                    const int k = kbase + kq * 64 + s2 * 16 + q * 8 + 2 * ac;
                    float2 v = *(const float2*)&rowp[k];
                    __half2 h2 = __floats2half2_rn(v.x, v.y);
                    wreg[cc][s2][nt][q] = *(uint32_t*)&h2;
                }
            }
    }

    const uint32_t as_base = (uint32_t)__cvta_generic_to_shared(As);
    const uint32_t rowoff_b = 2u * ((uint32_t)(lane & 15) * AW_STR + (uint32_t)(lane >> 4) * 8);

    // per-warp load: 16 rows (nh half) x 64 k of region (kq, cc)
    const int lrow = lane >> 3;      // 0..3
    const int lpc  = lane & 7;       // 0..7
    auto load_chunk = [&](int cc, int kbase) {
        __half* dst = As + ((size_t)kq * 4 + cc) * (32 * AW_STR);
        const int ksrc = kbase + kq * 64 + lpc * 8;
#pragma unroll
        for (int it = 0; it < 4; it++) {
            const int row = nh * 16 + it * 4 + lrow;     // 0..31 within region
            cp16cg(&dst[row * AW_STR + lpc * 8],
                   &g_h[(size_t)(B0 + row) * HID + ksrc]);
        }
        cp_commit();
    };

    const int kof[4] = { ((rot + 0) & 3) * 256, ((rot + 1) & 3) * 256,
                         ((rot + 2) & 3) * 256, ((rot + 3) & 3) * 256 };

    // packed x operands: element base (scaled x4 at use)
    const size_t xbase0 = (size_t)(B0 + m0) * TT * HID + hcol;
    const size_t xbase1 = (size_t)(B0 + m0 + 16) * TT * HID + hcol;
    uint2 xu0 = *(const uint2*)&g_xgp[xbase0 * 4];
    uint2 xu1 = *(const uint2*)&g_xgp[xbase1 * 4];
    float hv0 = 0.0f, hv1 = 0.0f;    // h(0) == 0

    unsigned phase = 0;

    for (int t = 0; t < TT; t++) {
        // issue this warp's 4 half-chunk loads
        load_chunk(0, kof[0]); load_chunk(1, kof[1]);
        load_chunk(2, kof[2]); load_chunk(3, kof[3]);

        float acc[2][3][4];
#pragma unroll
        for (int mt2 = 0; mt2 < 2; mt2++)
#pragma unroll
            for (int nt = 0; nt < 3; nt++)
#pragma unroll
                for (int q = 0; q < 4; q++) acc[mt2][nt][q] = 0.0f;

#pragma unroll
        for (int cc = 0; cc < 4; cc++) {
            if (cc == 0)      asm volatile("cp.async.wait_group 3;\n");
            else if (cc == 1) asm volatile("cp.async.wait_group 2;\n");
            else if (cc == 2) asm volatile("cp.async.wait_group 1;\n");
            else              asm volatile("cp.async.wait_group 0;\n");
            asm volatile("bar.sync %0, 64;" :: "r"(kq + 1) : "memory");

            const uint32_t buf = as_base + ((uint32_t)kq * 4 + cc) * AREG_B;
#pragma unroll
            for (int s2 = 0; s2 < 4; s2++) {
                const uint32_t kb_b = 2u * (uint32_t)(s2 * 16);
#pragma unroll
                for (int mt2 = 0; mt2 < 2; mt2++) {
                    uint32_t a0, a1, a2, a3;
                    const uint32_t addr = buf + 2u * (uint32_t)(mt2 * 16 * AW_STR)
                                        + kb_b + rowoff_b;
                    ldsm_x4(a0, a1, a2, a3, addr);
#pragma unroll
                    for (int nt = 0; nt < 3; nt++)
                        mma_f16(acc[mt2][nt], a0, a1, a2, a3,
                                wreg[cc][s2][nt][0], wreg[cc][s2][nt][1]);
                }
            }
        }

        // ---- write per-warp partials ----
#pragma unroll
        for (int mt2 = 0; mt2 < 2; mt2++)
#pragma unroll
            for (int nt = 0; nt < 3; nt++) {
                const int tile = mt2 * 3 + nt;
                *(float4*)&red[((w * 6 + tile) * 128) + lane * 4] =
                    make_float4(acc[mt2][nt][0], acc[mt2][nt][1],
                                acc[mt2][nt][2], acc[mt2][nt][3]);
            }
        __syncthreads();

        // ---- fused reduction + gate epilogue (2 outputs per thread) ----
        float h0, h1;
        {
            float A0[3], A1[3];
#pragma unroll
            for (int g = 0; g < 3; g++) {
                const int wb0 = nh_g[g] * 4;
                const int t0  = 0 * 3 + nt_g[g];
                const int t1  = 1 * 3 + nt_g[g];
                float s0 = 0.0f, s1 = 0.0f;
#pragma unroll
                for (int k2 = 0; k2 < 4; k2++) {
                    s0 += red[(((wb0 + k2) * 6 + t0) * 128) + rem_g[g]];
                    s1 += red[(((wb0 + k2) * 6 + t1) * 128) + rem_g[g]];
                }
                A0[g] = s0; A1[g] = s1;
            }

            const __half2 rz0 = *(__half2*)&xu0.x;
            const __half2 nn0 = *(__half2*)&xu0.y;
            const float r0 = sigmoidf_fast(__low2float(rz0)  + A0[0] + bR);
            const float z0 = sigmoidf_fast(__high2float(rz0) + A0[1] + bZ);
            const float n0 = tanhf_fast(__low2float(nn0) + r0 * (A0[2] + bN));
            h0 = (1.0f - z0) * n0 + z0 * hv0;
            const __half h0h = __float2half(h0);
            g_h[(size_t)(B0 + m0) * HID + hcol] = h0h;
            hv0 = __half2float(h0h);

            const __half2 rz1 = *(__half2*)&xu1.x;
            const __half2 nn1 = *(__half2*)&xu1.y;
            const float r1 = sigmoidf_fast(__low2float(rz1)  + A1[0] + bR);
            const float z1 = sigmoidf_fast(__high2float(rz1) + A1[1] + bZ);
            const float n1 = tanhf_fast(__low2float(nn1) + r1 * (A1[2] + bN));
            h1 = (1.0f - z1) * n1 + z1 * hv1;
            const __half h1h = __float2half(h1);
            g_h[(size_t)(B0 + m0 + 16) * HID + hcol] = h1h;
            hv1 = __half2float(h1h);
        }

        // ---- split barrier (64 blocks of this batch-half only) ----
        phase += 1;
        const unsigned target = phase * 64u;
        __syncthreads();                  // all g_h stores issued block-wide
        if (tid == 0) {
            unsigned old;
            asm volatile("atom.add.release.gpu.u32 %0, [%1], 1;"
                         : "=r"(old) : "l"(cnt) : "memory");
        }
        out[((size_t)(B0 + m0) * TT + t) * HID + hcol] = h0;
        out[((size_t)(B0 + m0 + 16) * TT + t) * HID + hcol] = h1;
        if (t + 1 < TT) {
            xu0 = *(const uint2*)&g_xgp[(xbase0 + (size_t)(t + 1) * HID) * 4];
            xu1 = *(const uint2*)&g_xgp[(xbase1 + (size_t)(t + 1) * HID) * 4];
        }
        if (tid == 0) {
            unsigned v;
            do {
                asm volatile("ld.acquire.gpu.u32 %0, [%1];"
                             : "=r"(v) : "l"(cnt) : "memory");
            } while (v < target);
        }
        __syncthreads();
    }
}

// ---------------------------------------------------------------------------
extern "C" void kernel_launch(void* const* d_in, const int* in_sizes, int n_in,
                              void* d_out, int out_size)
{
    const float* x     = (const float*)d_in[0];
    const float* W_i_r = (const float*)d_in[1];
    const float* b_i_r = (const float*)d_in[2];
    const float* W_h_r = (const float*)d_in[3];
    const float* b_h_r = (const float*)d_in[4];
    const float* W_i_z = (const float*)d_in[5];
    const float* b_i_z = (const float*)d_in[6];
    const float* W_h_z = (const float*)d_in[7];
    const float* b_h_z = (const float*)d_in[8];
    const float* W_i_n = (const float*)d_in[9];
    const float* b_i_n = (const float*)d_in[10];
    const float* W_h_n = (const float*)d_in[11];
    const float* b_h_n = (const float*)d_in[12];
    float* out = (float*)d_out;

    cudaFuncSetAttribute(recur_kernel, cudaFuncAttributeMaxDynamicSharedMemorySize,
                         RSMEM_BYTES);
    cudaFuncSetAttribute(igemm_f16_fused, cudaFuncAttributeMaxDynamicSharedMemorySize,
                         IGSM_BYTES);

    reset_kernel<<<(BATCH * HID + 255) / 256, 256>>>();

    convert_kernel<<<2048, 256>>>(x, W_i_r, W_i_z, W_i_n);

    dim3 ig(HID / 64, (BATCH * TT) / 128);
    igemm_f16_fused<<<ig, 256, IGSM_BYTES>>>(b_i_r, b_i_z, b_i_n);

    recur_kernel<<<RGRID, NTHR, RSMEM_BYTES>>>(W_h_r, W_h_z, W_h_n,
                                               b_h_r, b_h_z, b_h_n, out);
}

// round 17
// speedup vs baseline: 1.0528x; 1.0528x over previous
#include <cuda_runtime.h>
#include <cuda_fp16.h>
#include <math.h>
#include <stdint.h>

#define HID    1024
#define INP    512
#define BATCH  64
#define TT     512
#define RGRID  128
#define NTHR   256

// recurrence smem: shared (kq,cc) A regions + reduction buffer
#define AW_STR   72                         // halves per row (64 + 8 pad)
#define AREG_B   (32 * AW_STR * 2)          // one (kq,cc) region: 4608 B
#define A_TOT_B  (16 * AREG_B)              // 4 kq x 4 cc: 73728 B
#define RED_B    (8 * 6 * 128 * 4)          // 24576 B
#define RSMEM_BYTES (A_TOT_B + RED_B)

// igemm smem (fused 3-gate, k-chunk 64): xs[2][128*IG_STR] + ws[2][3][64*IG_STR]
#define IG_STR 72
#define IGS_X  (128 * IG_STR)
#define IGS_W  (64 * IG_STR)
#define IGSM_BYTES ((2 * IGS_X + 6 * IGS_W) * 2)   // 92160 B

// Scratch (device globals — allocation-free contract)
// packed input projections: [b][t][h][4] halves = {r, z, n, pad}
__device__ __half g_xgp[(size_t)BATCH * TT * HID * 4];
__device__ __half g_xh[(size_t)BATCH * TT * INP];      // fp16 copy of x
__device__ __half g_wih[3][HID * INP];                 // fp16 copies of W_i_{r,z,n}
__device__ __half g_h[BATCH * HID];                    // hidden state (fp16)
__device__ unsigned g_cnt[64];                         // split barrier counters (g_cnt[0], g_cnt[32])

// ---------------------------------------------------------------------------
__device__ __forceinline__ void mma_f16(float c[4], uint32_t a0, uint32_t a1,
                                        uint32_t a2, uint32_t a3,
                                        uint32_t b0, uint32_t b1) {
    asm volatile(
        "mma.sync.aligned.m16n8k16.row.col.f32.f16.f16.f32 "
        "{%0,%1,%2,%3}, {%4,%5,%6,%7}, {%8,%9}, {%0,%1,%2,%3};\n"
        : "+f"(c[0]), "+f"(c[1]), "+f"(c[2]), "+f"(c[3])
        : "r"(a0), "r"(a1), "r"(a2), "r"(a3), "r"(b0), "r"(b1));
}

__device__ __forceinline__ void ldsm_x4(uint32_t& r0, uint32_t& r1,
                                        uint32_t& r2, uint32_t& r3, uint32_t addr) {
    asm volatile("ldmatrix.sync.aligned.m8n8.x4.shared.b16 {%0,%1,%2,%3}, [%4];"
                 : "=r"(r0), "=r"(r1), "=r"(r2), "=r"(r3) : "r"(addr));
}

__device__ __forceinline__ void cp16ca(void* dst, const void* src) {
    uint32_t d = (uint32_t)__cvta_generic_to_shared(dst);
    asm volatile("cp.async.ca.shared.global [%0], [%1], 16;\n" :: "r"(d), "l"(src));
}
__device__ __forceinline__ void cp16cg(void* dst, const void* src) {
    uint32_t d = (uint32_t)__cvta_generic_to_shared(dst);
    asm volatile("cp.async.cg.shared.global [%0], [%1], 16;\n" :: "r"(d), "l"(src));
}
__device__ __forceinline__ void cp_commit() { asm volatile("cp.async.commit_group;\n"); }

__device__ __forceinline__ float sigmoidf_fast(float x) {
    return 1.0f / (1.0f + __expf(-x));
}
__device__ __forceinline__ float tanhf_fast(float x) {
    return 2.0f / (1.0f + __expf(-2.0f * x)) - 1.0f;
}

// ---------------------------------------------------------------------------
__global__ void reset_kernel()
{
    int i = blockIdx.x * blockDim.x + threadIdx.x;
    if (i < 64) g_cnt[i] = 0u;
    if (i < BATCH * HID) g_h[i] = __float2half(0.0f);
}

// ---------------------------------------------------------------------------
// Convert x and W_i_* to fp16 (one-time pre-pass).
__global__ __launch_bounds__(256) void convert_kernel(
    const float* __restrict__ x,
    const float* __restrict__ Wr, const float* __restrict__ Wz, const float* __restrict__ Wn)
{
    const size_t stride = (size_t)gridDim.x * blockDim.x;
    const size_t i0 = (size_t)blockIdx.x * blockDim.x + threadIdx.x;

    const size_t NX4 = (size_t)BATCH * TT * INP / 4;
    for (size_t j = i0; j < NX4; j += stride) {
        float4 v = ((const float4*)x)[j];
        ((__half2*)g_xh)[j * 2]     = __floats2half2_rn(v.x, v.y);
        ((__half2*)g_xh)[j * 2 + 1] = __floats2half2_rn(v.z, v.w);
    }
    const size_t NW4 = (size_t)HID * INP / 4;
    for (size_t j = i0; j < NW4; j += stride) {
        float4 a = ((const float4*)Wr)[j];
        float4 b = ((const float4*)Wz)[j];
        float4 c = ((const float4*)Wn)[j];
        ((__half2*)g_wih[0])[j * 2]     = __floats2half2_rn(a.x, a.y);
        ((__half2*)g_wih[0])[j * 2 + 1] = __floats2half2_rn(a.z, a.w);
        ((__half2*)g_wih[1])[j * 2]     = __floats2half2_rn(b.x, b.y);
        ((__half2*)g_wih[1])[j * 2 + 1] = __floats2half2_rn(b.z, b.w);
        ((__half2*)g_wih[2])[j * 2]     = __floats2half2_rn(c.x, c.y);
        ((__half2*)g_wih[2])[j * 2 + 1] = __floats2half2_rn(c.z, c.w);
    }
}

// ---------------------------------------------------------------------------
// Input projection GEMM, fused over the 3 gates (fp16 MMA m16n8k16).
// k-chunk 64 (8 chunks, 16 block syncs). Epilogue packs {r,z,n} fp16 into
// g_xgp[b][t][h][4].
__global__ __launch_bounds__(256) void igemm_f16_fused(
    const float* __restrict__ br, const float* __restrict__ bz, const float* __restrict__ bn)
{
    extern __shared__ __half igs[];
    __half* xs = igs;                  // [2][IGS_X]
    __half* ws = igs + 2 * IGS_X;      // [2][3][IGS_W]

    const int m0 = blockIdx.y * 128;
    const int n0 = blockIdx.x * 64;
    const int tid  = threadIdx.x;
    const int w    = tid >> 5;
    const int lane = tid & 31;
    const int ar   = lane >> 2;
    const int ac   = lane & 3;
    const int wm   = w >> 1;
    const int wn   = w & 1;

    float acc[3][2][4][4];
#pragma unroll
    for (int g = 0; g < 3; g++)
#pragma unroll
        for (int mt = 0; mt < 2; mt++)
#pragma unroll
            for (int nt = 0; nt < 4; nt++)
#pragma unroll
                for (int q = 0; q < 4; q++) acc[g][mt][nt][q] = 0.0f;

    auto load_chunk = [&](int c) {
        const int k0 = c * 64;
        __half* xd = xs + (c & 1) * IGS_X;
        // xs: 128 rows x 64 halves = 1024 x 16B pieces; 4 per thread
#pragma unroll
        for (int rep = 0; rep < 4; rep++) {
            const int job = tid + rep * 256;
            const int r = job >> 3, q = job & 7;
            cp16ca(&xd[r * IG_STR + q * 8], &g_xh[(size_t)(m0 + r) * INP + k0 + q * 8]);
        }
        // ws: 3 x 64 rows x 64 halves = 1536 pieces; 6 per thread
        __half* wd = ws + (c & 1) * (3 * IGS_W);
#pragma unroll
        for (int rep = 0; rep < 6; rep++) {
            const int job = tid + rep * 256;
            const int g  = job >> 9;
            const int rr = (job & 511) >> 3;
            const int q  = job & 7;
            cp16ca(&wd[g * IGS_W + rr * IG_STR + q * 8],
                   &g_wih[g][(size_t)(n0 + rr) * INP + k0 + q * 8]);
        }
        cp_commit();
    };

    load_chunk(0);

    for (int c = 0; c < INP / 64; c++) {
        asm volatile("cp.async.wait_group 0;\n");
        __syncthreads();
        if (c + 1 < INP / 64) load_chunk(c + 1);

        const __half* xb = xs + (c & 1) * IGS_X;
        const __half* wb = ws + (c & 1) * (3 * IGS_W);
        const uint32_t xb_base = (uint32_t)__cvta_generic_to_shared(xb);
        const uint32_t rowoff_b = 2u * ((uint32_t)(lane & 15) * IG_STR + (uint32_t)(lane >> 4) * 8);

#pragma unroll
        for (int s2 = 0; s2 < 4; s2++) {
            uint32_t afr[2][4];
#pragma unroll
            for (int mt = 0; mt < 2; mt++) {
                const uint32_t addr = xb_base
                    + 2u * (uint32_t)((wm * 32 + mt * 16) * IG_STR + s2 * 16)
                    + rowoff_b;
                ldsm_x4(afr[mt][0], afr[mt][1], afr[mt][2], afr[mt][3], addr);
            }
#pragma unroll
            for (int g = 0; g < 3; g++) {
#pragma unroll
                for (int nt = 0; nt < 4; nt++) {
                    const __half* bp = &wb[g * IGS_W
                        + (wn * 32 + nt * 8 + ar) * IG_STR + s2 * 16 + 2 * ac];
                    const uint32_t b0 = *(const uint32_t*)bp;
                    const uint32_t b1 = *(const uint32_t*)(bp + 8);
#pragma unroll
                    for (int mt = 0; mt < 2; mt++)
                        mma_f16(acc[g][mt][nt], afr[mt][0], afr[mt][1], afr[mt][2], afr[mt][3],
                                b0, b1);
                }
            }
        }
        __syncthreads();
    }

    // epilogue: pack {r,z,n} fp16 into g_xgp[b][t][h][4]
#pragma unroll
    for (int mt = 0; mt < 2; mt++) {
#pragma unroll
        for (int nt = 0; nt < 4; nt++) {
            const int h = n0 + wn * 32 + nt * 8 + ac * 2;
            const float br0 = br[h], br1 = br[h + 1];
            const float bz0 = bz[h], bz1 = bz[h + 1];
            const float bn0 = bn[h], bn1 = bn[h + 1];

#pragma unroll
            for (int half_ = 0; half_ < 2; half_++) {
                const int row = m0 + wm * 32 + mt * 16 + ar + half_ * 8;
                const int b = row >> 9, t = row & (TT - 1);
                const size_t base = ((size_t)b * TT + t) * (size_t)HID;
                const int q0 = half_ * 2;

                {
                    __half2 rz = __floats2half2_rn(acc[0][mt][nt][q0] + br0,
                                                   acc[1][mt][nt][q0] + bz0);
                    __half2 nn = __floats2half2_rn(acc[2][mt][nt][q0] + bn0, 0.0f);
                    uint2 u;
                    u.x = *(uint32_t*)&rz;
                    u.y = *(uint32_t*)&nn;
                    *(uint2*)&g_xgp[(base + h) * 4] = u;
                }
                {
                    __half2 rz = __floats2half2_rn(acc[0][mt][nt][q0 + 1] + br1,
                                                   acc[1][mt][nt][q0 + 1] + bz1);
                    __half2 nn = __floats2half2_rn(acc[2][mt][nt][q0 + 1] + bn1, 0.0f);
                    uint2 u;
                    u.x = *(uint32_t*)&rz;
                    u.y = *(uint32_t*)&nn;
                    *(uint2*)&g_xgp[(base + h + 1) * 4] = u;
                }
            }
        }
    }
}

// ---------------------------------------------------------------------------
// Persistent recurrence kernel — split barrier (two disjoint 64-block domains
// by batch-half) + packed fp16 x operands. Rotation is cg-based so each
// barrier domain retains full 4-way chunk stagger.
__global__ __launch_bounds__(NTHR, 1) void recur_kernel(
    const float* __restrict__ Wr, const float* __restrict__ Wz, const float* __restrict__ Wn,
    const float* __restrict__ bhr, const float* __restrict__ bhz, const float* __restrict__ bhn,
    float* __restrict__ out)
{
    extern __shared__ char smc[];
    __half* As  = (__half*)smc;                 // [4 kq][4 cc][32 rows][AW_STR]
    float*  red = (float*)(smc + A_TOT_B);      // [8][6][128]

    const int tid  = threadIdx.x;
    const int bid  = blockIdx.x;
    const int w    = tid >> 5;
    const int lane = tid & 31;
    const int ar   = lane >> 2;
    const int ac   = lane & 3;

    const int cg  = bid >> 1;
    const int bh  = bid & 1;
    const int H0  = cg * 16;
    const int B0  = bh * 32;
    const int nh  = w >> 2;          // n-half (0..1): rows nh*24..+24
    const int kq  = w & 3;           // k-quarter (0..3)
    const int rot = cg & 3;          // chunk rotation — full diversity per domain

    unsigned* const cnt = &g_cnt[bh * 32];   // split barrier counter

    // epilogue mapping: col ec (0..15), batches B0+m0 and B0+m0+16
    const int ec = tid & 15;
    const int m0 = tid >> 4;         // 0..15
    const int hcol = H0 + ec;
    const float bR = __ldg(&bhr[hcol]);
    const float bZ = __ldg(&bhz[hcol]);
    const float bN = __ldg(&bhn[hcol]);

    // per-gate reduction coordinates (j = g*16 + ec)
    int nh_g[3], nt_g[3], jr_g[3];
#pragma unroll
    for (int g = 0; g < 3; g++) {
        const int j = g * 16 + ec;
        nh_g[g] = (j >= 24) ? 1 : 0;
        const int loc = j - nh_g[g] * 24;
        nt_g[g] = loc >> 3;
        jr_g[g] = loc & 7;
    }
    int rem_g[3];
#pragma unroll
    for (int g = 0; g < 3; g++)
        rem_g[g] = (m0 & 7) * 16 + (jr_g[g] >> 1) * 4 + (m0 >> 3) * 2 + (jr_g[g] & 1);

    // ---- W fragments into registers; slot cc holds k-range ((rot+cc)&3)*256 ----
    uint32_t wreg[4][4][3][2];
#pragma unroll
    for (int cc = 0; cc < 4; cc++) {
        const int kbase = ((rot + cc) & 3) * 256;
#pragma unroll
        for (int s2 = 0; s2 < 4; s2++)
#pragma unroll
            for (int nt = 0; nt < 3; nt++) {
                const int j    = nh * 24 + nt * 8 + ar;
                const int gate = j >> 4;
                const int col  = j & 15;
                const float* __restrict__ Wp = (gate == 0) ? Wr : ((gate == 1) ? Wz : Wn);
                const float* rowp = &Wp[(size_t)(H0 + col) * HID];
#pragma unroll
                for (int q = 0; q < 2; q++) {
                    const int k = kbase + kq * 64 + s2 * 16 + q * 8 + 2 * ac;
                    float2 v = *(const float2*)&rowp[k];
                    __half2 h2 = __floats2half2_rn(v.x, v.y);
                    wreg[cc][s2][nt][q] = *(uint32_t*)&h2;
                }
            }
    }

    const uint32_t as_base = (uint32_t)__cvta_generic_to_shared(As);
    const uint32_t rowoff_b = 2u * ((uint32_t)(lane & 15) * AW_STR + (uint32_t)(lane >> 4) * 8);

    // per-warp load: 16 rows (nh half) x 64 k of region (kq, cc)
    const int lrow = lane >> 3;      // 0..3
    const int lpc  = lane & 7;       // 0..7
    auto load_chunk = [&](int cc, int kbase) {
        __half* dst = As + ((size_t)kq * 4 + cc) * (32 * AW_STR);
        const int ksrc = kbase + kq * 64 + lpc * 8;
#pragma unroll
        for (int it = 0; it < 4; it++) {
            const int row = nh * 16 + it * 4 + lrow;     // 0..31 within region
            cp16cg(&dst[row * AW_STR + lpc * 8],
                   &g_h[(size_t)(B0 + row) * HID + ksrc]);
        }
        cp_commit();
    };

    const int kof[4] = { ((rot + 0) & 3) * 256, ((rot + 1) & 3) * 256,
                         ((rot + 2) & 3) * 256, ((rot + 3) & 3) * 256 };

    // packed x operands
    const size_t xbase0 = (size_t)(B0 + m0) * TT * HID + hcol;
    const size_t xbase1 = (size_t)(B0 + m0 + 16) * TT * HID + hcol;
    uint2 xu0 = *(const uint2*)&g_xgp[xbase0 * 4];
    uint2 xu1 = *(const uint2*)&g_xgp[xbase1 * 4];
    float hv0 = 0.0f, hv1 = 0.0f;    // h(0) == 0

    unsigned phase = 0;

    for (int t = 0; t < TT; t++) {
        load_chunk(0, kof[0]); load_chunk(1, kof[1]);
        load_chunk(2, kof[2]); load_chunk(3, kof[3]);

        float acc[2][3][4];
#pragma unroll
        for (int mt2 = 0; mt2 < 2; mt2++)
#pragma unroll
            for (int nt = 0; nt < 3; nt++)
#pragma unroll
                for (int q = 0; q < 4; q++) acc[mt2][nt][q] = 0.0f;

#pragma unroll
        for (int cc = 0; cc < 4; cc++) {
            if (cc == 0)      asm volatile("cp.async.wait_group 3;\n");
            else if (cc == 1) asm volatile("cp.async.wait_group 2;\n");
            else if (cc == 2) asm volatile("cp.async.wait_group 1;\n");
            else              asm volatile("cp.async.wait_group 0;\n");
            asm volatile("bar.sync %0, 64;" :: "r"(kq + 1) : "memory");

            const uint32_t buf = as_base + ((uint32_t)kq * 4 + cc) * AREG_B;
#pragma unroll
            for (int s2 = 0; s2 < 4; s2++) {
                const uint32_t kb_b = 2u * (uint32_t)(s2 * 16);
#pragma unroll
                for (int mt2 = 0; mt2 < 2; mt2++) {
                    uint32_t a0, a1, a2, a3;
                    const uint32_t addr = buf + 2u * (uint32_t)(mt2 * 16 * AW_STR)
                                        + kb_b + rowoff_b;
                    ldsm_x4(a0, a1, a2, a3, addr);
#pragma unroll
                    for (int nt = 0; nt < 3; nt++)
                        mma_f16(acc[mt2][nt], a0, a1, a2, a3,
                                wreg[cc][s2][nt][0], wreg[cc][s2][nt][1]);
                }
            }
        }

        // ---- write per-warp partials ----
#pragma unroll
        for (int mt2 = 0; mt2 < 2; mt2++)
#pragma unroll
            for (int nt = 0; nt < 3; nt++) {
                const int tile = mt2 * 3 + nt;
                *(float4*)&red[((w * 6 + tile) * 128) + lane * 4] =
                    make_float4(acc[mt2][nt][0], acc[mt2][nt][1],
                                acc[mt2][nt][2], acc[mt2][nt][3]);
            }
        __syncthreads();

        // ---- fused reduction + gate epilogue (2 outputs per thread) ----
        float h0, h1;
        {
            float A0[3], A1[3];
#pragma unroll
            for (int g = 0; g < 3; g++) {
                const int wb0 = nh_g[g] * 4;
                const int t0  = 0 * 3 + nt_g[g];
                const int t1  = 1 * 3 + nt_g[g];
                float s0 = 0.0f, s1 = 0.0f;
#pragma unroll
                for (int k2 = 0; k2 < 4; k2++) {
                    s0 += red[(((wb0 + k2) * 6 + t0) * 128) + rem_g[g]];
                    s1 += red[(((wb0 + k2) * 6 + t1) * 128) + rem_g[g]];
                }
                A0[g] = s0; A1[g] = s1;
            }

            const __half2 rz0 = *(__half2*)&xu0.x;
            const __half2 nn0 = *(__half2*)&xu0.y;
            const float r0 = sigmoidf_fast(__low2float(rz0)  + A0[0] + bR);
            const float z0 = sigmoidf_fast(__high2float(rz0) + A0[1] + bZ);
            const float n0 = tanhf_fast(__low2float(nn0) + r0 * (A0[2] + bN));
            h0 = (1.0f - z0) * n0 + z0 * hv0;
            const __half h0h = __float2half(h0);
            g_h[(size_t)(B0 + m0) * HID + hcol] = h0h;
            hv0 = __half2float(h0h);

            const __half2 rz1 = *(__half2*)&xu1.x;
            const __half2 nn1 = *(__half2*)&xu1.y;
            const float r1 = sigmoidf_fast(__low2float(rz1)  + A1[0] + bR);
            const float z1 = sigmoidf_fast(__high2float(rz1) + A1[1] + bZ);
            const float n1 = tanhf_fast(__low2float(nn1) + r1 * (A1[2] + bN));
            h1 = (1.0f - z1) * n1 + z1 * hv1;
            const __half h1h = __float2half(h1);
            g_h[(size_t)(B0 + m0 + 16) * HID + hcol] = h1h;
            hv1 = __half2float(h1h);
        }

        // ---- split barrier (64 blocks of this batch-half only) ----
        phase += 1;
        const unsigned target = phase * 64u;
        __syncthreads();                  // all g_h stores issued block-wide
        if (tid == 0) {
            unsigned old;
            asm volatile("atom.add.release.gpu.u32 %0, [%1], 1;"
                         : "=r"(old) : "l"(cnt) : "memory");
        }
        out[((size_t)(B0 + m0) * TT + t) * HID + hcol] = h0;
        out[((size_t)(B0 + m0 + 16) * TT + t) * HID + hcol] = h1;
        if (t + 1 < TT) {
            xu0 = *(const uint2*)&g_xgp[(xbase0 + (size_t)(t + 1) * HID) * 4];
            xu1 = *(const uint2*)&g_xgp[(xbase1 + (size_t)(t + 1) * HID) * 4];
        }
        if (tid == 0) {
            unsigned v;
            do {
                asm volatile("ld.acquire.gpu.u32 %0, [%1];"
                             : "=r"(v) : "l"(cnt) : "memory");
            } while (v < target);
        }
        __syncthreads();
    }
}

// ---------------------------------------------------------------------------
extern "C" void kernel_launch(void* const* d_in, const int* in_sizes, int n_in,
                              void* d_out, int out_size)
{
    const float* x     = (const float*)d_in[0];
    const float* W_i_r = (const float*)d_in[1];
    const float* b_i_r = (const float*)d_in[2];
    const float* W_h_r = (const float*)d_in[3];
    const float* b_h_r = (const float*)d_in[4];
    const float* W_i_z = (const float*)d_in[5];
    const float* b_i_z = (const float*)d_in[6];
    const float* W_h_z = (const float*)d_in[7];
    const float* b_h_z = (const float*)d_in[8];
    const float* W_i_n = (const float*)d_in[9];
    const float* b_i_n = (const float*)d_in[10];
    const float* W_h_n = (const float*)d_in[11];
    const float* b_h_n = (const float*)d_in[12];
    float* out = (float*)d_out;

    cudaFuncSetAttribute(recur_kernel, cudaFuncAttributeMaxDynamicSharedMemorySize,
                         RSMEM_BYTES);
    cudaFuncSetAttribute(igemm_f16_fused, cudaFuncAttributeMaxDynamicSharedMemorySize,
                         IGSM_BYTES);

    reset_kernel<<<(BATCH * HID + 255) / 256, 256>>>();

    convert_kernel<<<2048, 256>>>(x, W_i_r, W_i_z, W_i_n);

    dim3 ig(HID / 64, (BATCH * TT) / 128);
    igemm_f16_fused<<<ig, 256, IGSM_BYTES>>>(b_i_r, b_i_z, b_i_n);

    recur_kernel<<<RGRID, NTHR, RSMEM_BYTES>>>(W_h_r, W_h_z, W_h_n,
                                               b_h_r, b_h_z, b_h_n, out);
}